// round 1
// baseline (speedup 1.0000x reference)
#include <cuda_runtime.h>
#include <math.h>

#define HWSZ 12544      // 112*112
#define IMGW 112
#define NB   16
#define CIN  64
#define EPSV 1e-5f

// ---- scratch (tiny) ----
__device__ float g_pooled[NB * 64];
__device__ float g_k1[NB * 64 * 64];   // [b][i][o], BN1 scale folded
__device__ float g_sum1[NB * 64];      // post-act x1 channel sums
__device__ float g_k2[NB * 64 * 9];    // [b][c][t], BN2 scale folded
__device__ float g_sum2[NB * 64];      // post-act x2 channel sums
__device__ float g_gates[NB * 128];

__device__ __forceinline__ float sigmoidf_(float x) { return 1.f / (1.f + expf(-x)); }

// ---------------------------------------------------------------
__global__ void zero_sums_kernel() {
    for (int i = threadIdx.x; i < NB * 64; i += 256) { g_sum1[i] = 0.f; g_sum2[i] = 0.f; }
}

// ---- mean over HW per (b,c): grid 1024 blocks x 256 ----
__global__ __launch_bounds__(256) void pool1_kernel(const float* __restrict__ x) {
    int bc = blockIdx.x;
    const float4* p = (const float4*)(x + (size_t)bc * HWSZ);
    float s = 0.f;
    for (int i = threadIdx.x; i < HWSZ / 4; i += 256) {
        float4 v = p[i];
        s += v.x + v.y + v.z + v.w;
    }
    for (int o = 16; o; o >>= 1) s += __shfl_xor_sync(0xffffffffu, s, o);
    __shared__ float red[8];
    if ((threadIdx.x & 31) == 0) red[threadIdx.x >> 5] = s;
    __syncthreads();
    if (threadIdx.x < 8) {
        s = red[threadIdx.x];
        for (int o = 4; o; o >>= 1) s += __shfl_xor_sync(0xffu, s, o);
        if (threadIdx.x == 0) g_pooled[bc] = s * (1.f / (float)HWSZ);
    }
}

// ---- r1 + mixed 1x1 kernel (BN1 scale folded): grid NB x 256 ----
__global__ __launch_bounds__(256) void build_k1_kernel(
    const float* __restrict__ rw1, const float* __restrict__ rb1,
    const float* __restrict__ w1,
    const float* __restrict__ g1, const float* __restrict__ v1) {
    int b = blockIdx.x;
    __shared__ float r1s[4];
    if (threadIdx.x < 4) {
        int e = threadIdx.x;
        float a = rb1[e];
        for (int i = 0; i < 64; i++) a += g_pooled[b * 64 + i] * rw1[e * 64 + i];
        r1s[e] = sigmoidf_(a);
    }
    __syncthreads();
    for (int idx = threadIdx.x; idx < 4096; idx += 256) {
        int i = idx >> 6, o = idx & 63;
        float a = 0.f;
#pragma unroll
        for (int e = 0; e < 4; e++) a += r1s[e] * w1[e * 4096 + o * 64 + i];
        float sc = g1[o] * rsqrtf(v1[o] + EPSV);
        g_k1[b * 4096 + idx] = a * sc;    // layout [i][o]
    }
}

// ---- dynamic 1x1 conv + BN + ReLU + channel-sum: grid (98, NB) x 256 ----
__global__ __launch_bounds__(256) void conv1_kernel(
    const float* __restrict__ x,
    const float* __restrict__ g1, const float* __restrict__ b1,
    const float* __restrict__ m1, const float* __restrict__ v1,
    float* __restrict__ out) {
    __shared__ float ks[4096];       // [i][o]
    __shared__ float xs[64 * 128];   // [i][px]
    int b = blockIdx.y;
    int p0 = blockIdx.x * 128;
    int tid = threadIdx.x;

    {
        const float4* ksrc = (const float4*)(g_k1 + b * 4096);
        float4* kdst = (float4*)ks;
        for (int i = tid; i < 1024; i += 256) kdst[i] = ksrc[i];
        for (int i = tid; i < 2048; i += 256) {
            int row = i >> 5, col = (i & 31) << 2;
            *(float4*)&xs[row * 128 + col] =
                *(const float4*)&x[((size_t)(b * 64 + row)) * HWSZ + p0 + col];
        }
    }
    __syncthreads();

    int og = (tid >> 5) << 3;    // 8 outputs per warp
    int px = (tid & 31) << 2;    // 4 pixels per lane
    float acc[8][4];
#pragma unroll
    for (int a = 0; a < 8; a++)
#pragma unroll
        for (int p = 0; p < 4; p++) acc[a][p] = 0.f;

#pragma unroll 16
    for (int i = 0; i < 64; i++) {
        float4 xv = *(const float4*)&xs[(i << 7) + px];
        float4 ka = *(const float4*)&ks[(i << 6) + og];
        float4 kb = *(const float4*)&ks[(i << 6) + og + 4];
        float kr[8] = {ka.x, ka.y, ka.z, ka.w, kb.x, kb.y, kb.z, kb.w};
        float xr[4] = {xv.x, xv.y, xv.z, xv.w};
#pragma unroll
        for (int a = 0; a < 8; a++)
#pragma unroll
            for (int p = 0; p < 4; p++) acc[a][p] = fmaf(kr[a], xr[p], acc[a][p]);
    }

    float ssum[8];
#pragma unroll
    for (int a = 0; a < 8; a++) {
        int o = og + a;
        float sc = g1[o] * rsqrtf(v1[o] + EPSV);
        float sh = b1[o] - m1[o] * sc;
        float4 r;
        r.x = fmaxf(acc[a][0] + sh, 0.f);
        r.y = fmaxf(acc[a][1] + sh, 0.f);
        r.z = fmaxf(acc[a][2] + sh, 0.f);
        r.w = fmaxf(acc[a][3] + sh, 0.f);
        *(float4*)&out[((size_t)(b * 128 + o)) * HWSZ + p0 + px] = r;
        ssum[a] = r.x + r.y + r.z + r.w;
    }
#pragma unroll
    for (int a = 0; a < 8; a++) {
        float s = ssum[a];
        for (int o2 = 16; o2; o2 >>= 1) s += __shfl_xor_sync(0xffffffffu, s, o2);
        if ((tid & 31) == 0) atomicAdd(&g_sum1[b * 64 + og + a], s);
    }
}

// ---- r2 + mixed 3x3 depthwise kernel (BN2 scale folded): grid NB x 256 ----
__global__ __launch_bounds__(256) void build_k2_kernel(
    const float* __restrict__ rw2, const float* __restrict__ rb2,
    const float* __restrict__ w2,
    const float* __restrict__ g2, const float* __restrict__ v2) {
    int b = blockIdx.x;
    __shared__ float r2s[4];
    if (threadIdx.x < 4) {
        int e = threadIdx.x;
        float a = rb2[e];
        for (int c = 0; c < 64; c++)
            a += g_sum1[b * 64 + c] * (1.f / (float)HWSZ) * rw2[e * 64 + c];
        r2s[e] = sigmoidf_(a);
    }
    __syncthreads();
    for (int idx = threadIdx.x; idx < 576; idx += 256) {
        int c = idx / 9;
        float a = 0.f;
#pragma unroll
        for (int e = 0; e < 4; e++) a += r2s[e] * w2[e * 576 + idx];
        float sc = g2[c] * rsqrtf(v2[c] + EPSV);
        g_k2[b * 576 + idx] = a * sc;
    }
}

// ---- dynamic 3x3 depthwise + BN + ReLU + channel-sum ----
// grid (4, 14, 1024), block (32, 8)
__global__ __launch_bounds__(256) void dw_kernel(
    const float* __restrict__ g2, const float* __restrict__ b2,
    const float* __restrict__ m2, const float* __restrict__ v2,
    float* __restrict__ out) {
    int bc = blockIdx.z;
    int b = bc >> 6, c = bc & 63;
    const float* in = out + ((size_t)(b * 128 + c)) * HWSZ;       // x1 channel
    float* op = out + ((size_t)(b * 128 + 64 + c)) * HWSZ;        // x2 channel
    __shared__ float kk[9];
    __shared__ float sh_bias;
    int tid = threadIdx.y * 32 + threadIdx.x;
    if (tid < 9) kk[tid] = g_k2[bc * 9 + tid];
    if (tid == 9) {
        float sc = g2[c] * rsqrtf(v2[c] + EPSV);
        sh_bias = b2[c] - m2[c] * sc;
    }
    __syncthreads();

    int x0 = blockIdx.x * 32 + threadIdx.x;
    int y0 = blockIdx.y * 8 + threadIdx.y;
    float val = 0.f;
    if (x0 < IMGW && y0 < IMGW) {
        float a = sh_bias;
#pragma unroll
        for (int dy = -1; dy <= 1; dy++) {
            int yy = y0 + dy;
            if (yy < 0 || yy >= IMGW) continue;
#pragma unroll
            for (int dx = -1; dx <= 1; dx++) {
                int xx = x0 + dx;
                if (xx < 0 || xx >= IMGW) continue;
                a = fmaf(kk[(dy + 1) * 3 + dx + 1], in[yy * IMGW + xx], a);
            }
        }
        val = fmaxf(a, 0.f);
        op[y0 * IMGW + x0] = val;
    }
    float s = val;
    for (int o = 16; o; o >>= 1) s += __shfl_xor_sync(0xffffffffu, s, o);
    __shared__ float red[8];
    if (threadIdx.x == 0) red[threadIdx.y] = s;
    __syncthreads();
    if (tid < 8) {
        s = red[tid];
        for (int o = 4; o; o >>= 1) s += __shfl_xor_sync(0xffu, s, o);
        if (tid == 0) atomicAdd(&g_sum2[bc], s);
    }
}

// ---- SE MLP -> gates: grid NB x 128 ----
__global__ __launch_bounds__(128) void se_kernel(
    const float* __restrict__ sw1, const float* __restrict__ sb1,
    const float* __restrict__ sw2, const float* __restrict__ sb2) {
    int b = blockIdx.x;
    int tid = threadIdx.x;
    __shared__ float sm[128];
    __shared__ float h[32];
    sm[tid] = (tid < 64 ? g_sum1[b * 64 + tid] : g_sum2[b * 64 + tid - 64]) * (1.f / (float)HWSZ);
    __syncthreads();
    if (tid < 32) {
        float a = sb1[tid];
        for (int c = 0; c < 128; c++) a += sw1[tid * 128 + c] * sm[c];
        h[tid] = fmaxf(a, 0.f);
    }
    __syncthreads();
    float a = sb2[tid];
#pragma unroll
    for (int j = 0; j < 32; j++) a += sw2[tid * 32 + j] * h[j];
    g_gates[b * 128 + tid] = sigmoidf_(a);
}

// ---- in-place gate scaling: grid 25088 x 256, one float4 per thread ----
__global__ __launch_bounds__(256) void scale_kernel(float* __restrict__ out) {
    int idx = blockIdx.x * 256 + threadIdx.x;       // float4 index, < 6422528
    int bc = idx / (HWSZ / 4);
    float g = __ldg(&g_gates[bc]);
    float4* p = ((float4*)out) + idx;
    float4 v = *p;
    v.x *= g; v.y *= g; v.z *= g; v.w *= g;
    *p = v;
}

// ---------------------------------------------------------------
extern "C" void kernel_launch(void* const* d_in, const int* in_sizes, int n_in,
                              void* d_out, int out_size) {
    const float* x    = (const float*)d_in[0];
    const float* rw1  = (const float*)d_in[1];
    const float* rb1  = (const float*)d_in[2];
    const float* w1   = (const float*)d_in[3];
    const float* bn1g = (const float*)d_in[4];
    const float* bn1b = (const float*)d_in[5];
    const float* bn1m = (const float*)d_in[6];
    const float* bn1v = (const float*)d_in[7];
    const float* rw2  = (const float*)d_in[8];
    const float* rb2  = (const float*)d_in[9];
    const float* w2   = (const float*)d_in[10];
    const float* bn2g = (const float*)d_in[11];
    const float* bn2b = (const float*)d_in[12];
    const float* bn2m = (const float*)d_in[13];
    const float* bn2v = (const float*)d_in[14];
    const float* sw1  = (const float*)d_in[15];
    const float* sb1  = (const float*)d_in[16];
    const float* sw2  = (const float*)d_in[17];
    const float* sb2  = (const float*)d_in[18];
    float* out = (float*)d_out;

    zero_sums_kernel<<<1, 256>>>();
    pool1_kernel<<<NB * 64, 256>>>(x);
    build_k1_kernel<<<NB, 256>>>(rw1, rb1, w1, bn1g, bn1v);
    conv1_kernel<<<dim3(HWSZ / 128, NB), 256>>>(x, bn1g, bn1b, bn1m, bn1v, out);
    build_k2_kernel<<<NB, 256>>>(rw2, rb2, w2, bn2g, bn2v);
    dw_kernel<<<dim3(4, 14, NB * 64), dim3(32, 8)>>>(bn2g, bn2b, bn2m, bn2v, out);
    se_kernel<<<NB, 128>>>(sw1, sb1, sw2, sb2);
    scale_kernel<<<(NB * 128 * (HWSZ / 4)) / 256, 256>>>(out);
}

// round 2
// speedup vs baseline: 1.5410x; 1.5410x over previous
#include <cuda_runtime.h>
#include <math.h>

#define HWSZ 12544      // 112*112
#define IMGW 112
#define NB   16
#define CIN  64
#define EPSV 1e-5f

// ---- scratch (tiny) ----
__device__ float g_pooled[NB * 64];
__device__ float g_k1[NB * 64 * 64];   // [b][i][o]
__device__ float g_sum1[NB * 64];      // post-act x1 channel sums
__device__ float g_k2[NB * 64 * 9];    // [b][c][t], BN2 scale folded
__device__ float g_sum2[NB * 64];      // post-act x2 channel sums
__device__ float g_gates[NB * 128];

__device__ __forceinline__ float sigmoidf_(float x) { return 1.f / (1.f + expf(-x)); }

// ---------------------------------------------------------------
__global__ void zero_sums_kernel() {
    for (int i = threadIdx.x; i < NB * 64; i += 256) { g_sum1[i] = 0.f; g_sum2[i] = 0.f; }
}

// ---- mean over HW per (b,c): grid 1024 blocks x 256 ----
__global__ __launch_bounds__(256) void pool1_kernel(const float* __restrict__ x) {
    int bc = blockIdx.x;
    const float4* p = (const float4*)(x + (size_t)bc * HWSZ);
    float s = 0.f;
    for (int i = threadIdx.x; i < HWSZ / 4; i += 256) {
        float4 v = p[i];
        s += v.x + v.y + v.z + v.w;
    }
    for (int o = 16; o; o >>= 1) s += __shfl_xor_sync(0xffffffffu, s, o);
    __shared__ float red[8];
    if ((threadIdx.x & 31) == 0) red[threadIdx.x >> 5] = s;
    __syncthreads();
    if (threadIdx.x < 8) {
        s = red[threadIdx.x];
        for (int o = 4; o; o >>= 1) s += __shfl_xor_sync(0xffu, s, o);
        if (threadIdx.x == 0) g_pooled[bc] = s * (1.f / (float)HWSZ);
    }
}

// ---- r1 + mixed 1x1 kernel (BN1 scale folded): grid NB x 256 ----
__global__ __launch_bounds__(256) void build_k1_kernel(
    const float* __restrict__ rw1, const float* __restrict__ rb1,
    const float* __restrict__ w1,
    const float* __restrict__ g1, const float* __restrict__ v1) {
    int b = blockIdx.x;
    __shared__ float r1s[4];
    if (threadIdx.x < 4) {
        int e = threadIdx.x;
        float a = rb1[e];
        for (int i = 0; i < 64; i++) a += g_pooled[b * 64 + i] * rw1[e * 64 + i];
        r1s[e] = sigmoidf_(a);
    }
    __syncthreads();
    for (int idx = threadIdx.x; idx < 4096; idx += 256) {
        int i = idx >> 6, o = idx & 63;
        float a = 0.f;
#pragma unroll
        for (int e = 0; e < 4; e++) a += r1s[e] * w1[e * 4096 + o * 64 + i];
        float sc = g1[o] * rsqrtf(v1[o] + EPSV);
        g_k1[b * 4096 + idx] = a * sc;    // layout [i][o]
    }
}

// ---- dynamic 1x1 conv + BN + ReLU + channel-sum ----
// tile: 64 outputs x 256 pixels per block; 8 warps, each warp 8 outputs x 256 px
// per lane: 8 outputs x 8 px (two float4 pixel groups)
// grid (49, NB) x 256, dynamic smem 80KB
extern __shared__ float conv1_smem[];
__global__ __launch_bounds__(256, 2) void conv1_kernel(
    const float* __restrict__ x,
    const float* __restrict__ g1, const float* __restrict__ b1,
    const float* __restrict__ m1, const float* __restrict__ v1,
    float* __restrict__ out) {
    float* ks = conv1_smem;          // [64i][64o] = 4096
    float* xs = conv1_smem + 4096;   // [64i][256px] = 16384
    int b = blockIdx.y;
    int p0 = blockIdx.x * 256;
    int tid = threadIdx.x;

    {
        const float4* ksrc = (const float4*)(g_k1 + b * 4096);
        float4* kdst = (float4*)ks;
#pragma unroll
        for (int i = 0; i < 4; i++) kdst[tid + 256 * i] = ksrc[tid + 256 * i];
        float4* xdst = (float4*)xs;
#pragma unroll
        for (int i = 0; i < 16; i++) {
            int idx = tid + 256 * i;           // f4 index in [0,4096)
            int row = idx >> 6, col = (idx & 63) << 2;
            xdst[idx] = *(const float4*)&x[((size_t)(b * 64 + row)) * HWSZ + p0 + col];
        }
    }
    __syncthreads();

    int og = (tid >> 5) << 3;    // warp -> 8 outputs
    int q0 = (tid & 31) << 2;    // lane -> pixels [q0..q0+3] and [q0+128..q0+131]
    float acc[8][8];
#pragma unroll
    for (int a = 0; a < 8; a++)
#pragma unroll
        for (int p = 0; p < 8; p++) acc[a][p] = 0.f;

#pragma unroll 8
    for (int i = 0; i < 64; i++) {
        float4 xa = *(const float4*)&xs[(i << 8) + q0];
        float4 xb = *(const float4*)&xs[(i << 8) + 128 + q0];
        float4 ka = *(const float4*)&ks[(i << 6) + og];
        float4 kb = *(const float4*)&ks[(i << 6) + og + 4];
        float kr[8] = {ka.x, ka.y, ka.z, ka.w, kb.x, kb.y, kb.z, kb.w};
        float xr[8] = {xa.x, xa.y, xa.z, xa.w, xb.x, xb.y, xb.z, xb.w};
#pragma unroll
        for (int a = 0; a < 8; a++)
#pragma unroll
            for (int p = 0; p < 8; p++) acc[a][p] = fmaf(kr[a], xr[p], acc[a][p]);
    }

#pragma unroll
    for (int a = 0; a < 8; a++) {
        int o = og + a;
        float sc = g1[o] * rsqrtf(v1[o] + EPSV);
        float sh = b1[o] - m1[o] * sc;
        float4 r0, r1q;
        r0.x = fmaxf(acc[a][0] + sh, 0.f);
        r0.y = fmaxf(acc[a][1] + sh, 0.f);
        r0.z = fmaxf(acc[a][2] + sh, 0.f);
        r0.w = fmaxf(acc[a][3] + sh, 0.f);
        r1q.x = fmaxf(acc[a][4] + sh, 0.f);
        r1q.y = fmaxf(acc[a][5] + sh, 0.f);
        r1q.z = fmaxf(acc[a][6] + sh, 0.f);
        r1q.w = fmaxf(acc[a][7] + sh, 0.f);
        float* op = out + ((size_t)(b * 128 + o)) * HWSZ + p0;
        *(float4*)&op[q0] = r0;
        *(float4*)&op[128 + q0] = r1q;
        float s = r0.x + r0.y + r0.z + r0.w + r1q.x + r1q.y + r1q.z + r1q.w;
        for (int o2 = 16; o2; o2 >>= 1) s += __shfl_xor_sync(0xffffffffu, s, o2);
        if ((tid & 31) == 0) atomicAdd(&g_sum1[b * 64 + o], s);
    }
}

// ---- r2 + mixed 3x3 depthwise kernel (BN2 scale folded): grid NB x 256 ----
__global__ __launch_bounds__(256) void build_k2_kernel(
    const float* __restrict__ rw2, const float* __restrict__ rb2,
    const float* __restrict__ w2,
    const float* __restrict__ g2, const float* __restrict__ v2) {
    int b = blockIdx.x;
    __shared__ float r2s[4];
    if (threadIdx.x < 4) {
        int e = threadIdx.x;
        float a = rb2[e];
        for (int c = 0; c < 64; c++)
            a += g_sum1[b * 64 + c] * (1.f / (float)HWSZ) * rw2[e * 64 + c];
        r2s[e] = sigmoidf_(a);
    }
    __syncthreads();
    for (int idx = threadIdx.x; idx < 576; idx += 256) {
        int c = idx / 9;
        float a = 0.f;
#pragma unroll
        for (int e = 0; e < 4; e++) a += r2s[e] * w2[e * 576 + idx];
        float sc = g2[c] * rsqrtf(v2[c] + EPSV);
        g_k2[b * 576 + idx] = a * sc;
    }
}

// ---- dynamic 3x3 depthwise + BN + ReLU + channel-sum ----
// grid (7 strips, NB*64), block 224 threads; strip = 16 rows x 112 cols
// smem tile: 18 rows x 120 floats (col x at [4+x], halo zeros at [3] and [116])
#define DWST 120
__global__ __launch_bounds__(224) void dw_kernel(
    const float* __restrict__ g2, const float* __restrict__ b2,
    const float* __restrict__ m2, const float* __restrict__ v2,
    float* __restrict__ out) {
    __shared__ float sm[18 * DWST];
    __shared__ float kk[9];
    __shared__ float sh_bias;
    __shared__ float red[7];

    int bc = blockIdx.y;
    int b = bc >> 6, c = bc & 63;
    const float* in = out + ((size_t)(b * 128 + c)) * HWSZ;       // x1 channel
    float* op = out + ((size_t)(b * 128 + 64 + c)) * HWSZ;        // x2 channel
    int tid = threadIdx.x;
    int y0 = blockIdx.x * 16;

    if (tid < 9) kk[tid] = g_k2[bc * 9 + tid];
    if (tid == 9) {
        float sc = g2[c] * rsqrtf(v2[c] + EPSV);
        sh_bias = b2[c] - m2[c] * sc;
    }
    // load 18 rows x 28 quads = 504 f4 with 224 threads (2 full + partial)
    for (int i = tid; i < 504; i += 224) {
        int r = i / 28, q = i % 28;
        int gy = y0 - 1 + r;
        float4 v;
        if (gy >= 0 && gy < IMGW) v = *(const float4*)&in[gy * IMGW + q * 4];
        else v = make_float4(0.f, 0.f, 0.f, 0.f);
        *(float4*)&sm[r * DWST + 4 + q * 4] = v;
    }
    // halo columns
    for (int r = tid; r < 18; r += 224) { sm[r * DWST + 3] = 0.f; sm[r * DWST + 116] = 0.f; }
    __syncthreads();

    int q = tid % 28;            // quad col
    int rr = tid / 28;           // 0..7
    int xb = 4 + q * 4;          // smem col of first output pixel
    float tsum = 0.f;

#pragma unroll
    for (int half = 0; half < 2; half++) {
        int orow = rr + half * 8;               // output row in strip (0..15)
        float acc0 = sh_bias, acc1 = sh_bias, acc2 = sh_bias, acc3 = sh_bias;
#pragma unroll
        for (int dr = 0; dr < 3; dr++) {
            const float* row = &sm[(orow + dr) * DWST];
            float l = row[xb - 1];
            float4 m = *(const float4*)&row[xb];
            float rgt = row[xb + 4];
            float k0 = kk[dr * 3 + 0], k1 = kk[dr * 3 + 1], k2 = kk[dr * 3 + 2];
            acc0 = fmaf(k0, l,   fmaf(k1, m.x, fmaf(k2, m.y, acc0)));
            acc1 = fmaf(k0, m.x, fmaf(k1, m.y, fmaf(k2, m.z, acc1)));
            acc2 = fmaf(k0, m.y, fmaf(k1, m.z, fmaf(k2, m.w, acc2)));
            acc3 = fmaf(k0, m.z, fmaf(k1, m.w, fmaf(k2, rgt, acc3)));
        }
        float4 r;
        r.x = fmaxf(acc0, 0.f); r.y = fmaxf(acc1, 0.f);
        r.z = fmaxf(acc2, 0.f); r.w = fmaxf(acc3, 0.f);
        *(float4*)&op[(y0 + orow) * IMGW + q * 4] = r;
        tsum += r.x + r.y + r.z + r.w;
    }

    // block reduction -> one atomic
    for (int o = 16; o; o >>= 1) tsum += __shfl_xor_sync(0xffffffffu, tsum, o);
    if ((tid & 31) == 0) red[tid >> 5] = tsum;
    __syncthreads();
    if (tid < 7) {
        float s = red[tid];
        for (int o = 4; o; o >>= 1) s += __shfl_xor_sync(0x7fu, s, o);
        if (tid == 0) atomicAdd(&g_sum2[bc], s);
    }
}

// ---- SE MLP -> gates: grid NB x 128 ----
__global__ __launch_bounds__(128) void se_kernel(
    const float* __restrict__ sw1, const float* __restrict__ sb1,
    const float* __restrict__ sw2, const float* __restrict__ sb2) {
    int b = blockIdx.x;
    int tid = threadIdx.x;
    __shared__ float sm[128];
    __shared__ float h[32];
    sm[tid] = (tid < 64 ? g_sum1[b * 64 + tid] : g_sum2[b * 64 + tid - 64]) * (1.f / (float)HWSZ);
    __syncthreads();
    if (tid < 32) {
        float a = sb1[tid];
        for (int c = 0; c < 128; c++) a += sw1[tid * 128 + c] * sm[c];
        h[tid] = fmaxf(a, 0.f);
    }
    __syncthreads();
    float a = sb2[tid];
#pragma unroll
    for (int j = 0; j < 32; j++) a += sw2[tid * 32 + j] * h[j];
    g_gates[b * 128 + tid] = sigmoidf_(a);
}

// ---- in-place gate scaling: one float4 per thread ----
__global__ __launch_bounds__(256) void scale_kernel(float* __restrict__ out) {
    int idx = blockIdx.x * 256 + threadIdx.x;       // float4 index, < 6422528
    int bc = idx / (HWSZ / 4);
    float g = __ldg(&g_gates[bc]);
    float4* p = ((float4*)out) + idx;
    float4 v = *p;
    v.x *= g; v.y *= g; v.z *= g; v.w *= g;
    *p = v;
}

// ---------------------------------------------------------------
extern "C" void kernel_launch(void* const* d_in, const int* in_sizes, int n_in,
                              void* d_out, int out_size) {
    const float* x    = (const float*)d_in[0];
    const float* rw1  = (const float*)d_in[1];
    const float* rb1  = (const float*)d_in[2];
    const float* w1   = (const float*)d_in[3];
    const float* bn1g = (const float*)d_in[4];
    const float* bn1b = (const float*)d_in[5];
    const float* bn1m = (const float*)d_in[6];
    const float* bn1v = (const float*)d_in[7];
    const float* rw2  = (const float*)d_in[8];
    const float* rb2  = (const float*)d_in[9];
    const float* w2   = (const float*)d_in[10];
    const float* bn2g = (const float*)d_in[11];
    const float* bn2b = (const float*)d_in[12];
    const float* bn2m = (const float*)d_in[13];
    const float* bn2v = (const float*)d_in[14];
    const float* sw1  = (const float*)d_in[15];
    const float* sb1  = (const float*)d_in[16];
    const float* sw2  = (const float*)d_in[17];
    const float* sb2  = (const float*)d_in[18];
    float* out = (float*)d_out;

    cudaFuncSetAttribute(conv1_kernel, cudaFuncAttributeMaxDynamicSharedMemorySize,
                         (4096 + 16384) * sizeof(float));

    zero_sums_kernel<<<1, 256>>>();
    pool1_kernel<<<NB * 64, 256>>>(x);
    build_k1_kernel<<<NB, 256>>>(rw1, rb1, w1, bn1g, bn1v);
    conv1_kernel<<<dim3(HWSZ / 256, NB), 256, (4096 + 16384) * sizeof(float)>>>(
        x, bn1g, bn1b, bn1m, bn1v, out);
    build_k2_kernel<<<NB, 256>>>(rw2, rb2, w2, bn2g, bn2v);
    dw_kernel<<<dim3(7, NB * 64), 224>>>(bn2g, bn2b, bn2m, bn2v, out);
    se_kernel<<<NB, 128>>>(sw1, sb1, sw2, sb2);
    scale_kernel<<<(NB * 128 * (HWSZ / 4)) / 256, 256>>>(out);
}